// round 1
// baseline (speedup 1.0000x reference)
#include <cuda_runtime.h>

#define BB 64
#define DD 256
#define NN 625
#define NH 8
#define DHD 32
#define M_TOT 40000          // BB*NN
#define SCALE 0.17677669529663687f   // 1/sqrt(32)
#define SP 628               // S row pitch in attention smem

// ---------------- scratch (device globals; no runtime allocation) ----------------
__device__ float g_q[BB*NH*NN*DHD];
__device__ float g_k[BB*NH*NN*DHD];
__device__ float g_v[BB*NH*NN*DHD];
__device__ float g_bias[NH*NN*NN];
__device__ float g_o[BB*NN*DD];

// ---------------- kernel 1: QKV GEMM ----------------
// C[m][c] = sum_k A[m][k] * w_qkv[k][c],  A[m][k] = x[b][k][n], m=b*625+n
// epilogue scatters into g_q/g_k/g_v with layout (b,h,n,dh); q scaled.
__global__ __launch_bounds__(256) void qkv_gemm(const float* __restrict__ x,
                                                const float* __restrict__ w) {
    __shared__ float As[16][128];
    __shared__ float Bs[16][64];
    const int m0 = blockIdx.x * 128;
    const int c0 = blockIdx.y * 64;
    const int tid = threadIdx.x;
    const int tx = tid & 15;       // 16 col-groups of 4
    const int ty = tid >> 4;       // 16 row-groups of 8
    const int b0 = m0 / NN;
    const int n0 = m0 - b0 * NN;

    float acc[8][4];
#pragma unroll
    for (int i = 0; i < 8; i++)
#pragma unroll
        for (int j = 0; j < 4; j++) acc[i][j] = 0.f;

    for (int k0 = 0; k0 < 256; k0 += 16) {
        // load A tile (coalesced along m; x is contiguous along n)
#pragma unroll
        for (int i = 0; i < 8; i++) {
            int e  = tid + i * 256;
            int kk = e >> 7;
            int ml = e & 127;
            int n = n0 + ml;
            int b = b0;
            if (n >= NN) { n -= NN; b++; }
            float val = 0.f;
            if (b < BB) val = x[(b * DD + k0 + kk) * NN + n];
            As[kk][ml] = val;
        }
        // load B tile
#pragma unroll
        for (int i = 0; i < 4; i++) {
            int e  = tid + i * 256;
            int kk = e >> 6;
            int c  = e & 63;
            Bs[kk][c] = w[(k0 + kk) * 768 + c0 + c];
        }
        __syncthreads();
#pragma unroll
        for (int kk = 0; kk < 16; kk++) {
            float a[8], bv[4];
            *(float4*)&a[0] = *(const float4*)&As[kk][ty * 8];
            *(float4*)&a[4] = *(const float4*)&As[kk][ty * 8 + 4];
            *(float4*)&bv[0] = *(const float4*)&Bs[kk][tx * 4];
#pragma unroll
            for (int i = 0; i < 8; i++)
#pragma unroll
                for (int j = 0; j < 4; j++) acc[i][j] = fmaf(a[i], bv[j], acc[i][j]);
        }
        __syncthreads();
    }

    // epilogue: t is uniform per block (c0 is a multiple of 64, 64 | 256)
    const int t = c0 >> 8;                 // 0=q 1=k 2=v
    float* dst = (t == 0) ? g_q : (t == 1) ? g_k : g_v;
    const float mul = (t == 0) ? SCALE : 1.0f;
#pragma unroll
    for (int i = 0; i < 8; i++) {
        int ml = ty * 8 + i;
        int n = n0 + ml;
        int b = b0;
        if (n >= NN) { n -= NN; b++; }
        if (b >= BB) continue;
#pragma unroll
        for (int j = 0; j < 4; j++) {
            int c  = c0 + tx * 4 + j;
            int dd = c & 255;
            int h  = dd >> 5;
            int e  = dd & 31;
            dst[((b * NH + h) * NN + n) * DHD + e] = acc[i][j] * mul;
        }
    }
}

// ---------------- kernel 2: bias gather ----------------
__global__ __launch_bounds__(256) void bias_fill(const float* __restrict__ bt,
                                                 const int* __restrict__ rel) {
    int p = blockIdx.x * 256 + threadIdx.x;
    if (p >= NN * NN) return;
    int idx = rel[p];
#pragma unroll
    for (int h = 0; h < NH; h++)
        g_bias[h * (NN * NN) + p] = bt[idx * NH + h];
}

// ---------------- kernel 3: fused attention ----------------
// grid (10, 8, 64): (row_tile, head, batch). 64 rows per block; full score row in smem.
__global__ __launch_bounds__(256) void attn_kernel() {
    extern __shared__ float sm[];
    float* S   = sm;                         // 64 * SP
    float* Qs  = sm + 64 * SP;               // 64 * 33
    float* KVs = Qs + 64 * 33;               // 64 * 33

    const int i0 = blockIdx.x * 64;
    const int h  = blockIdx.y;
    const int b  = blockIdx.z;
    const int tid = threadIdx.x;

    const float* qb = g_q + ((b * NH + h) * NN) * DHD;
    const float* kb = g_k + ((b * NH + h) * NN) * DHD;
    const float* vb = g_v + ((b * NH + h) * NN) * DHD;
    const float* biash = g_bias + h * (NN * NN);

    // load Q tile (zero-padded)
#pragma unroll
    for (int r = 0; r < 8; r++) {
        int e  = tid + r * 256;
        int il = e >> 5;
        int d  = e & 31;
        int ig = i0 + il;
        Qs[il * 33 + d] = (ig < NN) ? qb[ig * DHD + d] : 0.f;
    }

    // ---- S = Q K^T + bias ----
    const int tx = tid & 15;    // 16 col-groups of 4
    const int ty = tid >> 4;    // 16 row-groups of 4
    for (int j0 = 0; j0 < NN; j0 += 64) {
        __syncthreads();
#pragma unroll
        for (int r = 0; r < 8; r++) {
            int e  = tid + r * 256;
            int jl = e >> 5;
            int d  = e & 31;
            int jg = j0 + jl;
            KVs[jl * 33 + d] = (jg < NN) ? kb[jg * DHD + d] : 0.f;
        }
        __syncthreads();
        float acc[4][4];
#pragma unroll
        for (int i = 0; i < 4; i++)
#pragma unroll
            for (int j = 0; j < 4; j++) acc[i][j] = 0.f;
#pragma unroll
        for (int d = 0; d < 32; d++) {
            float a0 = Qs[(ty * 4 + 0) * 33 + d];
            float a1 = Qs[(ty * 4 + 1) * 33 + d];
            float a2 = Qs[(ty * 4 + 2) * 33 + d];
            float a3 = Qs[(ty * 4 + 3) * 33 + d];
            float b0 = KVs[(tx * 4 + 0) * 33 + d];
            float b1 = KVs[(tx * 4 + 1) * 33 + d];
            float b2 = KVs[(tx * 4 + 2) * 33 + d];
            float b3 = KVs[(tx * 4 + 3) * 33 + d];
            acc[0][0] = fmaf(a0, b0, acc[0][0]); acc[0][1] = fmaf(a0, b1, acc[0][1]);
            acc[0][2] = fmaf(a0, b2, acc[0][2]); acc[0][3] = fmaf(a0, b3, acc[0][3]);
            acc[1][0] = fmaf(a1, b0, acc[1][0]); acc[1][1] = fmaf(a1, b1, acc[1][1]);
            acc[1][2] = fmaf(a1, b2, acc[1][2]); acc[1][3] = fmaf(a1, b3, acc[1][3]);
            acc[2][0] = fmaf(a2, b0, acc[2][0]); acc[2][1] = fmaf(a2, b1, acc[2][1]);
            acc[2][2] = fmaf(a2, b2, acc[2][2]); acc[2][3] = fmaf(a2, b3, acc[2][3]);
            acc[3][0] = fmaf(a3, b0, acc[3][0]); acc[3][1] = fmaf(a3, b1, acc[3][1]);
            acc[3][2] = fmaf(a3, b2, acc[3][2]); acc[3][3] = fmaf(a3, b3, acc[3][3]);
        }
#pragma unroll
        for (int i = 0; i < 4; i++) {
            int il = ty * 4 + i;
            int ig = i0 + il;
#pragma unroll
            for (int j = 0; j < 4; j++) {
                int jg = j0 + tx * 4 + j;
                if (jg < NN) {
                    float val = 0.f;
                    if (ig < NN) val = acc[i][j] + biash[ig * NN + jg];
                    S[il * SP + jg] = val;
                }
            }
        }
    }
    __syncthreads();

    // ---- row softmax (4 threads / row) ----
    {
        const int row = tid >> 2;
        const int sub = tid & 3;
        float* Sr = S + row * SP;
        float mx = -1e30f;
        for (int j = sub; j < NN; j += 4) mx = fmaxf(mx, Sr[j]);
        mx = fmaxf(mx, __shfl_xor_sync(0xffffffffu, mx, 1));
        mx = fmaxf(mx, __shfl_xor_sync(0xffffffffu, mx, 2));
        float sum = 0.f;
        for (int j = sub; j < NN; j += 4) {
            float e = __expf(Sr[j] - mx);
            Sr[j] = e;
            sum += e;
        }
        sum += __shfl_xor_sync(0xffffffffu, sum, 1);
        sum += __shfl_xor_sync(0xffffffffu, sum, 2);
        float inv = 1.f / sum;
        for (int j = sub; j < NN; j += 4) Sr[j] *= inv;
    }
    __syncthreads();

    // ---- O = P V ----
    const int e  = tid & 31;
    const int rg = tid >> 5;          // 8 row-groups of 8
    float oacc[8];
#pragma unroll
    for (int r = 0; r < 8; r++) oacc[r] = 0.f;

    for (int j0 = 0; j0 < NN; j0 += 64) {
        __syncthreads();
#pragma unroll
        for (int r = 0; r < 8; r++) {
            int ee = tid + r * 256;
            int jl = ee >> 5;
            int d  = ee & 31;
            int jg = j0 + jl;
            KVs[jl * 33 + d] = (jg < NN) ? vb[jg * DHD + d] : 0.f;
        }
        __syncthreads();
        int jlim = NN - j0;
        if (jlim >= 64) {
#pragma unroll 4
            for (int jj = 0; jj < 64; jj++) {
                float vv = KVs[jj * 33 + e];
#pragma unroll
                for (int r = 0; r < 8; r++)
                    oacc[r] = fmaf(S[(rg * 8 + r) * SP + j0 + jj], vv, oacc[r]);
            }
        } else {
            for (int jj = 0; jj < jlim; jj++) {
                float vv = KVs[jj * 33 + e];
#pragma unroll
                for (int r = 0; r < 8; r++)
                    oacc[r] = fmaf(S[(rg * 8 + r) * SP + j0 + jj], vv, oacc[r]);
            }
        }
    }

#pragma unroll
    for (int r = 0; r < 8; r++) {
        int ig = i0 + rg * 8 + r;
        if (ig < NN) g_o[(b * NN + ig) * DD + h * DHD + e] = oacc[r];
    }
}

// ---------------- kernel 4: out projection + transpose ----------------
// out[b][dd][n] = sum_k g_o[b][n][k] * w_out[k][dd]
__global__ __launch_bounds__(256) void out_gemm(const float* __restrict__ w,
                                                float* __restrict__ out) {
    __shared__ float As[16][132];
    __shared__ float Bs[16][64];
    __shared__ float Cs[128][65];
    const int m0 = blockIdx.x * 128;
    const int c0 = blockIdx.y * 64;
    const int tid = threadIdx.x;
    const int tx = tid & 15;
    const int ty = tid >> 4;
    const int b0 = m0 / NN;
    const int n0 = m0 - b0 * NN;

    float acc[8][4];
#pragma unroll
    for (int i = 0; i < 8; i++)
#pragma unroll
        for (int j = 0; j < 4; j++) acc[i][j] = 0.f;

    for (int k0 = 0; k0 < 256; k0 += 16) {
        // load A tile: g_o row-major, vectorized float4 per thread
#pragma unroll
        for (int half = 0; half < 2; half++) {
            int ml = (tid >> 2) + half * 64;
            int kq = tid & 3;
            int m = m0 + ml;
            float4 av = make_float4(0.f, 0.f, 0.f, 0.f);
            if (m < M_TOT) av = *(const float4*)&g_o[m * DD + k0 + kq * 4];
            As[kq * 4 + 0][ml] = av.x;
            As[kq * 4 + 1][ml] = av.y;
            As[kq * 4 + 2][ml] = av.z;
            As[kq * 4 + 3][ml] = av.w;
        }
#pragma unroll
        for (int i = 0; i < 4; i++) {
            int e  = tid + i * 256;
            int kk = e >> 6;
            int c  = e & 63;
            Bs[kk][c] = w[(k0 + kk) * DD + c0 + c];
        }
        __syncthreads();
#pragma unroll
        for (int kk = 0; kk < 16; kk++) {
            float a[8], bv[4];
            *(float4*)&a[0] = *(const float4*)&As[kk][ty * 8];
            *(float4*)&a[4] = *(const float4*)&As[kk][ty * 8 + 4];
            *(float4*)&bv[0] = *(const float4*)&Bs[kk][tx * 4];
#pragma unroll
            for (int i = 0; i < 8; i++)
#pragma unroll
                for (int j = 0; j < 4; j++) acc[i][j] = fmaf(a[i], bv[j], acc[i][j]);
        }
        __syncthreads();
    }

    // stage into smem, then write transposed (coalesced along n)
#pragma unroll
    for (int i = 0; i < 8; i++)
#pragma unroll
        for (int j = 0; j < 4; j++)
            Cs[ty * 8 + i][tx * 4 + j] = acc[i][j];
    __syncthreads();

#pragma unroll
    for (int r = 0; r < 32; r++) {
        int idx = tid + r * 256;
        int cl = idx >> 7;          // 0..63
        int ml = idx & 127;
        int n = n0 + ml;
        int b = b0;
        if (n >= NN) { n -= NN; b++; }
        if (b < BB)
            out[(b * DD + c0 + cl) * NN + n] = Cs[ml][cl];
    }
}

// ---------------- launch ----------------
extern "C" void kernel_launch(void* const* d_in, const int* in_sizes, int n_in,
                              void* d_out, int out_size) {
    const float* x      = (const float*)d_in[0];
    const float* w_qkv  = (const float*)d_in[1];
    const float* w_out  = (const float*)d_in[2];
    const float* btable = (const float*)d_in[3];
    const int*   rel    = (const int*)d_in[4];
    float* out = (float*)d_out;

    static bool attr_set = false;
    // (idempotent attribute set; host-side, not a stream op, deterministic)
    size_t attn_smem = (size_t)(64 * SP + 2 * 64 * 33) * sizeof(float);
    cudaFuncSetAttribute(attn_kernel, cudaFuncAttributeMaxDynamicSharedMemorySize,
                         (int)attn_smem);
    (void)attr_set;

    qkv_gemm<<<dim3((M_TOT + 127) / 128, 768 / 64), 256>>>(x, w_qkv);
    bias_fill<<<(NN * NN + 255) / 256, 256>>>(btable, rel);
    attn_kernel<<<dim3((NN + 63) / 64, NH, BB), 256, attn_smem>>>();
    out_gemm<<<dim3((M_TOT + 127) / 128, DD / 64), 256>>>(w_out, out);
}

// round 2
// speedup vs baseline: 1.3653x; 1.3653x over previous
#include <cuda_runtime.h>

#define BB 64
#define DD 256
#define NN 625
#define NH 8
#define DHD 32
#define M_TOT 40000                    // BB*NN
#define SCALE 0.17677669529663687f     // 1/sqrt(32)
#define SP 640                         // S row pitch (floats), padded, 16B aligned
#define QP 36                          // Q smem pitch
#define BP 628                         // bias row pitch (floats), 16B aligned
#define NEGBIG (-1e30f)

// ---------------- scratch (device globals; no runtime allocation) ----------------
__device__ float g_q[BB*NH*NN*DHD];
__device__ float g_k[BB*NH*NN*DHD];
__device__ float g_v[BB*NH*NN*DHD];
__device__ float g_bias[NH*NN*BP];
__device__ float g_o[BB*NN*DD];

// ---------------- kernel 1: QKV GEMM (128x128 tile, 8x8/thread) ----------------
__global__ __launch_bounds__(256) void qkv_gemm(const float* __restrict__ x,
                                                const float* __restrict__ w) {
    __shared__ float As[16][128];
    __shared__ float Bs[16][128];
    const int m0 = blockIdx.x * 128;
    const int c0 = blockIdx.y * 128;
    const int tid = threadIdx.x;
    const int tx = tid & 15;       // 16 col-groups of 8
    const int ty = tid >> 4;       // 16 row-groups of 8
    const int b0 = m0 / NN;
    const int n0 = m0 - b0 * NN;

    float acc[8][8];
#pragma unroll
    for (int i = 0; i < 8; i++)
#pragma unroll
        for (int j = 0; j < 8; j++) acc[i][j] = 0.f;

    for (int k0 = 0; k0 < 256; k0 += 16) {
        // A tile: 16 x 128, gathered from x (coalesced along n)
#pragma unroll
        for (int i = 0; i < 8; i++) {
            int e  = tid + i * 256;
            int kk = e >> 7;
            int ml = e & 127;
            int n = n0 + ml;
            int b = b0;
            if (n >= NN) { n -= NN; b++; }
            float val = 0.f;
            if (b < BB) val = x[(b * DD + k0 + kk) * NN + n];
            As[kk][ml] = val;
        }
        // B tile: 16 x 128, float4
#pragma unroll
        for (int half = 0; half < 2; half++) {
            int kk = (tid >> 5) + half * 8;
            int c  = (tid & 31) * 4;
            *(float4*)&Bs[kk][c] = *(const float4*)&w[(k0 + kk) * 768 + c0 + c];
        }
        __syncthreads();
#pragma unroll 8
        for (int kk = 0; kk < 16; kk++) {
            float a[8], bv[8];
            *(float4*)&a[0]  = *(const float4*)&As[kk][ty * 8];
            *(float4*)&a[4]  = *(const float4*)&As[kk][ty * 8 + 4];
            *(float4*)&bv[0] = *(const float4*)&Bs[kk][tx * 8];
            *(float4*)&bv[4] = *(const float4*)&Bs[kk][tx * 8 + 4];
#pragma unroll
            for (int i = 0; i < 8; i++)
#pragma unroll
                for (int j = 0; j < 8; j++) acc[i][j] = fmaf(a[i], bv[j], acc[i][j]);
        }
        __syncthreads();
    }

    // epilogue: 8 consecutive cols per thread live in one q/k/v block, one (h) pair
    const int cbase = c0 + tx * 8;
    const int t = cbase >> 8;                 // 0=q 1=k 2=v
    float* dst = (t == 0) ? g_q : (t == 1) ? g_k : g_v;
    const float mul = (t == 0) ? SCALE : 1.0f;
    const int h  = (cbase >> 5) & 7;
    const int e0 = cbase & 31;                // multiple of 8
#pragma unroll
    for (int i = 0; i < 8; i++) {
        int ml = ty * 8 + i;
        int n = n0 + ml;
        int b = b0;
        if (n >= NN) { n -= NN; b++; }
        if (b >= BB) continue;
        float* p = dst + ((b * NH + h) * NN + n) * DHD + e0;
        float4 v0, v1;
        v0.x = acc[i][0] * mul; v0.y = acc[i][1] * mul;
        v0.z = acc[i][2] * mul; v0.w = acc[i][3] * mul;
        v1.x = acc[i][4] * mul; v1.y = acc[i][5] * mul;
        v1.z = acc[i][6] * mul; v1.w = acc[i][7] * mul;
        *(float4*)p = v0;
        *(float4*)(p + 4) = v1;
    }
}

// ---------------- kernel 2: bias gather (pitched output) ----------------
__global__ __launch_bounds__(256) void bias_fill(const float* __restrict__ bt,
                                                 const int* __restrict__ rel) {
    int j = blockIdx.x * 256 + threadIdx.x;
    int i = blockIdx.y;
    if (j >= NN) return;
    int idx = rel[i * NN + j];
#pragma unroll
    for (int h = 0; h < NH; h++)
        g_bias[(h * NN + i) * BP + j] = bt[idx * NH + h];
}

// ---------------- kernel 3: fused attention ----------------
// grid (10, 8, 64). 64 rows per block, full score row in smem (pitch 640).
__global__ __launch_bounds__(256) void attn_kernel() {
    extern __shared__ float sm[];
    float* S   = sm;                           // 64 * 640
    float* Qs  = sm + 64 * SP;                 // 64 * 36
    float* KVs = Qs + 64 * QP;                 // 256 * 32 (K swizzled / V plain)

    const int i0 = blockIdx.x * 64;
    const int h  = blockIdx.y;
    const int b  = blockIdx.z;
    const int tid = threadIdx.x;

    const float* qb = g_q + ((b * NH + h) * NN) * DHD;
    const float* kb = g_k + ((b * NH + h) * NN) * DHD;
    const float* vb = g_v + ((b * NH + h) * NN) * DHD;
    const float* biash = g_bias + h * NN * BP;

    // load Q tile (zero-padded rows)
#pragma unroll
    for (int r = 0; r < 8; r++) {
        int e  = tid + r * 256;
        int il = e >> 5;
        int d  = e & 31;
        int ig = i0 + il;
        Qs[il * QP + d] = (ig < NN) ? qb[ig * DHD + d] : 0.f;
    }

    // ---- S = Q K^T + bias ----
    {
        const int tx = tid & 31;     // 32 col-groups of 8 (j-tile = 256)
        const int ty = tid >> 5;     // 8 row-groups of 8
        for (int tile = 0; tile < 3; tile++) {
            const int j0 = tile * 256;
            __syncthreads();
            // K tile load, XOR-swizzled 16B chunks
#pragma unroll
            for (int i = 0; i < 8; i++) {
                int idx = tid + i * 256;
                int j = idx >> 3;
                int c = idx & 7;
                int jg = j0 + j;
                float4 kv = make_float4(0.f, 0.f, 0.f, 0.f);
                if (jg < NN) kv = *(const float4*)&kb[jg * DHD + c * 4];
                *(float4*)&KVs[j * 32 + ((c ^ ((j >> 3) & 7)) << 2)] = kv;
            }
            __syncthreads();

            float acc[8][8];
#pragma unroll
            for (int i = 0; i < 8; i++)
#pragma unroll
                for (int j = 0; j < 8; j++) acc[i][j] = 0.f;

#pragma unroll 2
            for (int dq = 0; dq < 8; dq++) {
                float4 q4[8], k4[8];
#pragma unroll
                for (int i = 0; i < 8; i++)
                    q4[i] = *(const float4*)&Qs[(ty * 8 + i) * QP + dq * 4];
#pragma unroll
                for (int j = 0; j < 8; j++)
                    k4[j] = *(const float4*)&KVs[(tx * 8 + j) * 32 + ((dq ^ (tx & 7)) << 2)];
#pragma unroll
                for (int i = 0; i < 8; i++)
#pragma unroll
                    for (int j = 0; j < 8; j++) {
                        acc[i][j] = fmaf(q4[i].x, k4[j].x, acc[i][j]);
                        acc[i][j] = fmaf(q4[i].y, k4[j].y, acc[i][j]);
                        acc[i][j] = fmaf(q4[i].z, k4[j].z, acc[i][j]);
                        acc[i][j] = fmaf(q4[i].w, k4[j].w, acc[i][j]);
                    }
            }

            // store S (+bias), -1e30 sentinels in padding
            const int jg0 = j0 + tx * 8;
            if (jg0 < SP) {
#pragma unroll
                for (int i = 0; i < 8; i++) {
                    int il = ty * 8 + i;
                    int ig = i0 + il;
                    const float* brow = biash + ig * BP;
                    float4 v0, v1;
                    if (ig < NN) {
                        float bv[8];
#pragma unroll
                        for (int q = 0; q < 8; q++) {
                            int jg = jg0 + q;
                            bv[q] = (jg < NN) ? brow[jg] : 0.f;
                        }
                        v0.x = (jg0 + 0 < NN) ? acc[i][0] + bv[0] : NEGBIG;
                        v0.y = (jg0 + 1 < NN) ? acc[i][1] + bv[1] : NEGBIG;
                        v0.z = (jg0 + 2 < NN) ? acc[i][2] + bv[2] : NEGBIG;
                        v0.w = (jg0 + 3 < NN) ? acc[i][3] + bv[3] : NEGBIG;
                        v1.x = (jg0 + 4 < NN) ? acc[i][4] + bv[4] : NEGBIG;
                        v1.y = (jg0 + 5 < NN) ? acc[i][5] + bv[5] : NEGBIG;
                        v1.z = (jg0 + 6 < NN) ? acc[i][6] + bv[6] : NEGBIG;
                        v1.w = (jg0 + 7 < NN) ? acc[i][7] + bv[7] : NEGBIG;
                    } else {
                        v0 = make_float4(NEGBIG, NEGBIG, NEGBIG, NEGBIG);
                        v1 = v0;
                    }
                    *(float4*)&S[il * SP + jg0]     = v0;
                    *(float4*)&S[il * SP + jg0 + 4] = v1;
                }
            }
        }
    }
    __syncthreads();

    // ---- row softmax (4 threads / row, float4) ----
    {
        const int row = tid >> 2;
        const int sub = tid & 3;
        float4* Sr = (float4*)(S + row * SP);
        float mx = NEGBIG;
#pragma unroll 4
        for (int t = sub; t < SP / 4; t += 4) {
            float4 v = Sr[t];
            mx = fmaxf(mx, fmaxf(fmaxf(v.x, v.y), fmaxf(v.z, v.w)));
        }
        mx = fmaxf(mx, __shfl_xor_sync(0xffffffffu, mx, 1));
        mx = fmaxf(mx, __shfl_xor_sync(0xffffffffu, mx, 2));
        float sum = 0.f;
#pragma unroll 4
        for (int t = sub; t < SP / 4; t += 4) {
            float4 v = Sr[t];
            v.x = __expf(v.x - mx); v.y = __expf(v.y - mx);
            v.z = __expf(v.z - mx); v.w = __expf(v.w - mx);
            Sr[t] = v;
            sum += v.x + v.y + v.z + v.w;
        }
        sum += __shfl_xor_sync(0xffffffffu, sum, 1);
        sum += __shfl_xor_sync(0xffffffffu, sum, 2);
        float inv = 1.f / sum;
#pragma unroll 4
        for (int t = sub; t < SP / 4; t += 4) {
            float4 v = Sr[t];
            v.x *= inv; v.y *= inv; v.z *= inv; v.w *= inv;
            Sr[t] = v;
        }
    }

    // ---- O = P V (4 j-slices, 8 rows x 4 cols per thread) ----
    const int eg = tid & 7;            // e0 = eg*4
    const int rg = (tid >> 3) & 7;     // rows rg*8 .. +7
    const int sl = tid >> 6;           // j slice 0..3
    float4 oacc[8];
#pragma unroll
    for (int r = 0; r < 8; r++) oacc[r] = make_float4(0.f, 0.f, 0.f, 0.f);

    for (int tile = 0; tile < 3; tile++) {
        const int j0 = tile * 256;
        const int cnt = (tile == 2) ? 128 : 256;
        __syncthreads();
        // V tile load (plain layout, rows of 32 floats)
        const int nf4 = cnt * 8;
        for (int idx = tid; idx < nf4; idx += 256) {
            int j = idx >> 3;
            int c = idx & 7;
            int jg = j0 + j;
            float4 vv = make_float4(0.f, 0.f, 0.f, 0.f);
            if (jg < NN) vv = *(const float4*)&vb[jg * DHD + c * 4];
            *(float4*)&KVs[j * 32 + c * 4] = vv;
        }
        __syncthreads();
        const int sc = cnt >> 2;
        const int jbeg = sl * sc;
        for (int jj = jbeg; jj < jbeg + sc; jj += 4) {
            float4 vv0 = *(const float4*)&KVs[(jj + 0) * 32 + eg * 4];
            float4 vv1 = *(const float4*)&KVs[(jj + 1) * 32 + eg * 4];
            float4 vv2 = *(const float4*)&KVs[(jj + 2) * 32 + eg * 4];
            float4 vv3 = *(const float4*)&KVs[(jj + 3) * 32 + eg * 4];
#pragma unroll
            for (int r = 0; r < 8; r++) {
                float4 sv = *(const float4*)&S[(rg * 8 + r) * SP + j0 + jj];
                oacc[r].x = fmaf(sv.x, vv0.x, oacc[r].x);
                oacc[r].y = fmaf(sv.x, vv0.y, oacc[r].y);
                oacc[r].z = fmaf(sv.x, vv0.z, oacc[r].z);
                oacc[r].w = fmaf(sv.x, vv0.w, oacc[r].w);
                oacc[r].x = fmaf(sv.y, vv1.x, oacc[r].x);
                oacc[r].y = fmaf(sv.y, vv1.y, oacc[r].y);
                oacc[r].z = fmaf(sv.y, vv1.z, oacc[r].z);
                oacc[r].w = fmaf(sv.y, vv1.w, oacc[r].w);
                oacc[r].x = fmaf(sv.z, vv2.x, oacc[r].x);
                oacc[r].y = fmaf(sv.z, vv2.y, oacc[r].y);
                oacc[r].z = fmaf(sv.z, vv2.z, oacc[r].z);
                oacc[r].w = fmaf(sv.z, vv2.w, oacc[r].w);
                oacc[r].x = fmaf(sv.w, vv3.x, oacc[r].x);
                oacc[r].y = fmaf(sv.w, vv3.y, oacc[r].y);
                oacc[r].z = fmaf(sv.w, vv3.z, oacc[r].z);
                oacc[r].w = fmaf(sv.w, vv3.w, oacc[r].w);
            }
        }
    }
    __syncthreads();
    // reduce across 4 slices via KVs buffer (4*64*32 floats = 32KB exactly)
#pragma unroll
    for (int r = 0; r < 8; r++)
        *(float4*)&KVs[(sl * 64 + rg * 8 + r) * 32 + eg * 4] = oacc[r];
    __syncthreads();
    {
        const int row = tid >> 2;
        const int e0  = (tid & 3) * 8;
        const int ig  = i0 + row;
        if (ig < NN) {
            float* dst = g_o + (b * NN + ig) * DD + h * DHD + e0;
#pragma unroll
            for (int g = 0; g < 2; g++) {
                float4 a = *(const float4*)&KVs[(0 * 64 + row) * 32 + e0 + g * 4];
                float4 a1 = *(const float4*)&KVs[(1 * 64 + row) * 32 + e0 + g * 4];
                float4 a2 = *(const float4*)&KVs[(2 * 64 + row) * 32 + e0 + g * 4];
                float4 a3 = *(const float4*)&KVs[(3 * 64 + row) * 32 + e0 + g * 4];
                a.x += a1.x + a2.x + a3.x;
                a.y += a1.y + a2.y + a3.y;
                a.z += a1.z + a2.z + a3.z;
                a.w += a1.w + a2.w + a3.w;
                *(float4*)(dst + g * 4) = a;
            }
        }
    }
}

// ---------------- kernel 4: out projection + transpose ----------------
__global__ __launch_bounds__(256) void out_gemm(const float* __restrict__ w,
                                                float* __restrict__ out) {
    __shared__ float As[16][132];
    __shared__ float Bs[16][64];
    __shared__ float Cs[128][65];
    const int m0 = blockIdx.x * 128;
    const int c0 = blockIdx.y * 64;
    const int tid = threadIdx.x;
    const int tx = tid & 15;
    const int ty = tid >> 4;
    const int b0 = m0 / NN;
    const int n0 = m0 - b0 * NN;

    float acc[8][4];
#pragma unroll
    for (int i = 0; i < 8; i++)
#pragma unroll
        for (int j = 0; j < 4; j++) acc[i][j] = 0.f;

    for (int k0 = 0; k0 < 256; k0 += 16) {
#pragma unroll
        for (int half = 0; half < 2; half++) {
            int ml = (tid >> 2) + half * 64;
            int kq = tid & 3;
            int m = m0 + ml;
            float4 av = make_float4(0.f, 0.f, 0.f, 0.f);
            if (m < M_TOT) av = *(const float4*)&g_o[m * DD + k0 + kq * 4];
            As[kq * 4 + 0][ml] = av.x;
            As[kq * 4 + 1][ml] = av.y;
            As[kq * 4 + 2][ml] = av.z;
            As[kq * 4 + 3][ml] = av.w;
        }
#pragma unroll
        for (int i = 0; i < 4; i++) {
            int e  = tid + i * 256;
            int kk = e >> 6;
            int c  = e & 63;
            Bs[kk][c] = w[(k0 + kk) * DD + c0 + c];
        }
        __syncthreads();
#pragma unroll 8
        for (int kk = 0; kk < 16; kk++) {
            float a[8], bv[4];
            *(float4*)&a[0] = *(const float4*)&As[kk][ty * 8];
            *(float4*)&a[4] = *(const float4*)&As[kk][ty * 8 + 4];
            *(float4*)&bv[0] = *(const float4*)&Bs[kk][tx * 4];
#pragma unroll
            for (int i = 0; i < 8; i++)
#pragma unroll
                for (int j = 0; j < 4; j++) acc[i][j] = fmaf(a[i], bv[j], acc[i][j]);
        }
        __syncthreads();
    }

#pragma unroll
    for (int i = 0; i < 8; i++)
#pragma unroll
        for (int j = 0; j < 4; j++)
            Cs[ty * 8 + i][tx * 4 + j] = acc[i][j];
    __syncthreads();

#pragma unroll
    for (int r = 0; r < 32; r++) {
        int idx = tid + r * 256;
        int cl = idx >> 7;
        int ml = idx & 127;
        int n = n0 + ml;
        int bb = b0;
        if (n >= NN) { n -= NN; bb++; }
        if (bb < BB)
            out[(bb * DD + c0 + cl) * NN + n] = Cs[ml][cl];
    }
}

// ---------------- launch ----------------
extern "C" void kernel_launch(void* const* d_in, const int* in_sizes, int n_in,
                              void* d_out, int out_size) {
    const float* x      = (const float*)d_in[0];
    const float* w_qkv  = (const float*)d_in[1];
    const float* w_out  = (const float*)d_in[2];
    const float* btable = (const float*)d_in[3];
    const int*   rel    = (const int*)d_in[4];
    float* out = (float*)d_out;

    size_t attn_smem = (size_t)(64 * SP + 64 * QP + 256 * 32) * sizeof(float);
    cudaFuncSetAttribute(attn_kernel, cudaFuncAttributeMaxDynamicSharedMemorySize,
                         (int)attn_smem);

    qkv_gemm<<<dim3((M_TOT + 127) / 128, 768 / 128), 256>>>(x, w_qkv);
    bias_fill<<<dim3((NN + 255) / 256, NN), 256>>>(btable, rel);
    attn_kernel<<<dim3((NN + 63) / 64, NH, BB), 256, attn_smem>>>();
    out_gemm<<<dim3((M_TOT + 127) / 128, DD / 64), 256>>>(w_out, out);
}

// round 3
// speedup vs baseline: 2.1013x; 1.5391x over previous
#include <cuda_runtime.h>

#define BB 64
#define DD 256
#define NN 625
#define NH 8
#define DHD 32
#define M_TOT 40000                    // BB*NN
#define SCALE 0.17677669529663687f     // 1/sqrt(32)
#define BP 628                         // bias row pitch (floats)

// attention tiling
#define IT 32                          // i-tile rows per block
#define SPW 644                        // S pitch (words): 4 mod 32 -> conflict-free frag loads
#define KVP 36                         // K/V/Q smem pitch (words)
#define NJT 5                          // j tiles of 128 (640 padded)

// ---------------- scratch (device globals; no runtime allocation) ----------------
__device__ float g_q[BB*NH*NN*DHD];
__device__ float g_k[BB*NH*NN*DHD];
__device__ float g_v[BB*NH*NN*DHD];
__device__ float g_bias[NH*NN*BP];
__device__ float g_o[BB*NN*DD];

// ---------------- helpers ----------------
__device__ __forceinline__ unsigned f2tf32(float x) {
    unsigned r;
    asm("cvt.rna.tf32.f32 %0, %1;" : "=r"(r) : "f"(x));
    return r;
}

__device__ __forceinline__ void mma_tf32(float& c0, float& c1, float& c2, float& c3,
                                         unsigned a0, unsigned a1, unsigned a2, unsigned a3,
                                         unsigned b0, unsigned b1) {
    asm volatile("mma.sync.aligned.m16n8k8.row.col.f32.tf32.tf32.f32 "
                 "{%0,%1,%2,%3},{%4,%5,%6,%7},{%8,%9},{%0,%1,%2,%3};"
                 : "+f"(c0), "+f"(c1), "+f"(c2), "+f"(c3)
                 : "r"(a0), "r"(a1), "r"(a2), "r"(a3), "r"(b0), "r"(b1));
}

// exp on fma/alu pipes (no MUFU): 2^(x*log2e), |x| small here
__device__ __forceinline__ float fexp(float x) {
    float y = x * 1.4426950408889634f;
    float t = y + 12582912.0f;                    // 1.5*2^23 round trick
    int   n = __float_as_int(t) - 0x4B400000;
    float f = y - (t - 12582912.0f);
    float p = 1.3333558146e-3f;
    p = fmaf(p, f, 9.6181291076e-3f);
    p = fmaf(p, f, 5.5504108665e-2f);
    p = fmaf(p, f, 2.4022650696e-1f);
    p = fmaf(p, f, 6.9314718056e-1f);
    p = fmaf(p, f, 1.0f);
    return __int_as_float(__float_as_int(p) + (n << 23));
}

// ---------------- kernel 1: QKV GEMM (128x128 tile, 8x8/thread) ----------------
__global__ __launch_bounds__(256) void qkv_gemm(const float* __restrict__ x,
                                                const float* __restrict__ w) {
    __shared__ float As[16][128];
    __shared__ float Bs[16][128];
    const int m0 = blockIdx.x * 128;
    const int c0 = blockIdx.y * 128;
    const int tid = threadIdx.x;
    const int tx = tid & 15;
    const int ty = tid >> 4;
    const int b0 = m0 / NN;
    const int n0 = m0 - b0 * NN;

    float acc[8][8];
#pragma unroll
    for (int i = 0; i < 8; i++)
#pragma unroll
        for (int j = 0; j < 8; j++) acc[i][j] = 0.f;

    for (int k0 = 0; k0 < 256; k0 += 16) {
#pragma unroll
        for (int i = 0; i < 8; i++) {
            int e  = tid + i * 256;
            int kk = e >> 7;
            int ml = e & 127;
            int n = n0 + ml;
            int b = b0;
            if (n >= NN) { n -= NN; b++; }
            float val = 0.f;
            if (b < BB) val = x[(b * DD + k0 + kk) * NN + n];
            As[kk][ml] = val;
        }
#pragma unroll
        for (int half = 0; half < 2; half++) {
            int kk = (tid >> 5) + half * 8;
            int c  = (tid & 31) * 4;
            *(float4*)&Bs[kk][c] = *(const float4*)&w[(k0 + kk) * 768 + c0 + c];
        }
        __syncthreads();
#pragma unroll 8
        for (int kk = 0; kk < 16; kk++) {
            float a[8], bv[8];
            *(float4*)&a[0]  = *(const float4*)&As[kk][ty * 8];
            *(float4*)&a[4]  = *(const float4*)&As[kk][ty * 8 + 4];
            *(float4*)&bv[0] = *(const float4*)&Bs[kk][tx * 8];
            *(float4*)&bv[4] = *(const float4*)&Bs[kk][tx * 8 + 4];
#pragma unroll
            for (int i = 0; i < 8; i++)
#pragma unroll
                for (int j = 0; j < 8; j++) acc[i][j] = fmaf(a[i], bv[j], acc[i][j]);
        }
        __syncthreads();
    }

    const int cbase = c0 + tx * 8;
    const int t = cbase >> 8;
    float* dst = (t == 0) ? g_q : (t == 1) ? g_k : g_v;
    const float mul = (t == 0) ? SCALE : 1.0f;
    const int h  = (cbase >> 5) & 7;
    const int e0 = cbase & 31;
#pragma unroll
    for (int i = 0; i < 8; i++) {
        int ml = ty * 8 + i;
        int n = n0 + ml;
        int b = b0;
        if (n >= NN) { n -= NN; b++; }
        if (b >= BB) continue;
        float* p = dst + ((b * NH + h) * NN + n) * DHD + e0;
        float4 v0, v1;
        v0.x = acc[i][0] * mul; v0.y = acc[i][1] * mul;
        v0.z = acc[i][2] * mul; v0.w = acc[i][3] * mul;
        v1.x = acc[i][4] * mul; v1.y = acc[i][5] * mul;
        v1.z = acc[i][6] * mul; v1.w = acc[i][7] * mul;
        *(float4*)p = v0;
        *(float4*)(p + 4) = v1;
    }
}

// ---------------- kernel 2: bias gather (pitched output) ----------------
__global__ __launch_bounds__(256) void bias_fill(const float* __restrict__ bt,
                                                 const int* __restrict__ rel) {
    int j = blockIdx.x * 256 + threadIdx.x;
    int i = blockIdx.y;
    if (j >= NN) return;
    int idx = rel[i * NN + j];
#pragma unroll
    for (int h = 0; h < NH; h++)
        g_bias[(h * NN + i) * BP + j] = bt[idx * NH + h];
}

// ---------------- kernel 3: fused attention (tf32 mma + fused exp) ----------------
// grid (20, 8, 64): (i_tile of 32 rows, head, batch). 256 threads = 8 warps.
// Phase S: S = exp(Q K^T + bias), row sums accumulated on the fly (no max-sub).
// Phase PV: O = (S @ V) * (1/rowsum).
__global__ __launch_bounds__(256) void attn_kernel() {
    extern __shared__ unsigned smu[];
    unsigned* S   = smu;                      // IT * SPW  (tf32 bits of exp(S))
    unsigned* Qs  = S + IT * SPW;             // IT * KVP  (tf32)
    unsigned* KVs = Qs + IT * KVP;            // 128 * KVP (tf32)
    float* rpart  = (float*)(KVs + 128 * KVP);  // IT * 4
    float* rinv   = rpart + IT * 4;             // IT

    const int i0 = blockIdx.x * IT;
    const int h  = blockIdx.y;
    const int bz = blockIdx.z;
    const int tid = threadIdx.x;
    const int w    = tid >> 5;
    const int lane = tid & 31;
    const int g    = lane >> 2;       // groupID
    const int tig  = lane & 3;        // thread in group

    const float* qb = g_q + ((bz * NH + h) * NN) * DHD;
    const float* kb = g_k + ((bz * NH + h) * NN) * DHD;
    const float* vb = g_v + ((bz * NH + h) * NN) * DHD;
    const float* biash = g_bias + h * NN * BP;

    // ---- load Q tile (32x32), tf32, pitch 36 ----
    {
        int il = tid >> 3;
        int dq = tid & 7;
        int ig = i0 + il;
        float4 qv = make_float4(0.f, 0.f, 0.f, 0.f);
        if (ig < NN) qv = *(const float4*)&qb[ig * DHD + dq * 4];
        unsigned* p = &Qs[il * KVP + dq * 4];
        p[0] = f2tf32(qv.x); p[1] = f2tf32(qv.y);
        p[2] = f2tf32(qv.z); p[3] = f2tf32(qv.w);
    }
    __syncthreads();

    // ---- S phase ----
    // warp mapping: rowgrp = w&1 (16 rows), colq = w>>1 (32-col quarter of 128-tile)
    const int rb   = (w & 1) * 16;
    const int colq = w >> 1;

    // preload A fragments (Q, constant across j tiles): a[kstep][0..3]
    unsigned aq[4][4];
#pragma unroll
    for (int ks = 0; ks < 4; ks++) {
        int d0 = ks * 8;
        aq[ks][0] = Qs[(rb + g)     * KVP + d0 + tig];
        aq[ks][1] = Qs[(rb + g + 8) * KVP + d0 + tig];
        aq[ks][2] = Qs[(rb + g)     * KVP + d0 + tig + 4];
        aq[ks][3] = Qs[(rb + g + 8) * KVP + d0 + tig + 4];
    }

    float rsum0 = 0.f, rsum1 = 0.f;

    for (int tile = 0; tile < NJT; tile++) {
        const int t0 = tile * 128;
        __syncthreads();
        // load K tile (128x32) tf32
#pragma unroll
        for (int it = 0; it < 4; it++) {
            int idx = tid + it * 256;
            int j  = idx >> 3;
            int dq = idx & 7;
            int jg = t0 + j;
            float4 kv = make_float4(0.f, 0.f, 0.f, 0.f);
            if (jg < NN) kv = *(const float4*)&kb[jg * DHD + dq * 4];
            unsigned* p = &KVs[j * KVP + dq * 4];
            p[0] = f2tf32(kv.x); p[1] = f2tf32(kv.y);
            p[2] = f2tf32(kv.z); p[3] = f2tf32(kv.w);
        }
        __syncthreads();

#pragma unroll
        for (int ct = 0; ct < 4; ct++) {
            const int jb = colq * 32 + ct * 8;       // in-tile col base of this 8-wide frag
            float c0 = 0.f, c1 = 0.f, c2 = 0.f, c3 = 0.f;
#pragma unroll
            for (int ks = 0; ks < 4; ks++) {
                int d0 = ks * 8;
                unsigned b0 = KVs[(jb + g) * KVP + d0 + tig];
                unsigned b1 = KVs[(jb + g) * KVP + d0 + tig + 4];
                mma_tf32(c0, c1, c2, c3, aq[ks][0], aq[ks][1], aq[ks][2], aq[ks][3], b0, b1);
            }
            // epilogue: +bias, exp, row-sum, tf32 store
            const int jg  = t0 + jb + tig * 2;       // global col of c0
            const int rl0 = rb + g, rl1 = rl0 + 8;
            const int ig0 = i0 + rl0, ig1 = i0 + rl1;
            float bx0 = 0.f, by0 = 0.f, bx1 = 0.f, by1 = 0.f;
            if (jg < NN) {
                if (ig0 < NN) { float2 t2 = *(const float2*)&biash[ig0 * BP + jg]; bx0 = t2.x; by0 = t2.y; }
                if (ig1 < NN) { float2 t2 = *(const float2*)&biash[ig1 * BP + jg]; bx1 = t2.x; by1 = t2.y; }
            }
            float e00 = 0.f, e01 = 0.f, e10 = 0.f, e11 = 0.f;
            if (jg < NN)     { e00 = fexp(c0 + bx0); e10 = fexp(c2 + bx1); }
            if (jg + 1 < NN) { e01 = fexp(c1 + by0); e11 = fexp(c3 + by1); }
            rsum0 += e00 + e01;
            rsum1 += e10 + e11;
            uint2 u0; u0.x = f2tf32(e00); u0.y = f2tf32(e01);
            uint2 u1; u1.x = f2tf32(e10); u1.y = f2tf32(e11);
            *(uint2*)&S[rl0 * SPW + jg - 0] = u0;    // jg is global col (t0+jb+2*tig)
            *(uint2*)&S[rl1 * SPW + jg - 0] = u1;
        }
    }

    // ---- row-sum reduction ----
    rsum0 += __shfl_xor_sync(0xffffffffu, rsum0, 1);
    rsum0 += __shfl_xor_sync(0xffffffffu, rsum0, 2);
    rsum1 += __shfl_xor_sync(0xffffffffu, rsum1, 1);
    rsum1 += __shfl_xor_sync(0xffffffffu, rsum1, 2);
    if (tig == 0) {
        rpart[(rb + g)     * 4 + colq] = rsum0;
        rpart[(rb + g + 8) * 4 + colq] = rsum1;
    }
    __syncthreads();
    if (tid < IT)
        rinv[tid] = 1.f / (rpart[tid * 4] + rpart[tid * 4 + 1] +
                           rpart[tid * 4 + 2] + rpart[tid * 4 + 3]);

    // ---- PV phase ----
    // warp mapping: rowgrp2 = w&1 (16 rows), nf = w>>1 -> 8-col output frag
    const int rb2 = (w & 1) * 16;
    const int n0  = (w >> 1) * 8;
    float o0 = 0.f, o1 = 0.f, o2 = 0.f, o3 = 0.f;

    for (int tile = 0; tile < NJT; tile++) {
        const int t0 = tile * 128;
        __syncthreads();
        // load V tile (128x32) tf32
#pragma unroll
        for (int it = 0; it < 4; it++) {
            int idx = tid + it * 256;
            int j  = idx >> 3;
            int dq = idx & 7;
            int jg = t0 + j;
            float4 vv = make_float4(0.f, 0.f, 0.f, 0.f);
            if (jg < NN) vv = *(const float4*)&vb[jg * DHD + dq * 4];
            unsigned* p = &KVs[j * KVP + dq * 4];
            p[0] = f2tf32(vv.x); p[1] = f2tf32(vv.y);
            p[2] = f2tf32(vv.z); p[3] = f2tf32(vv.w);
        }
        __syncthreads();

#pragma unroll 4
        for (int ks = 0; ks < 16; ks++) {
            const int colg = t0 + ks * 8;
            unsigned a0 = S[(rb2 + g)     * SPW + colg + tig];
            unsigned a1 = S[(rb2 + g + 8) * SPW + colg + tig];
            unsigned a2 = S[(rb2 + g)     * SPW + colg + tig + 4];
            unsigned a3 = S[(rb2 + g + 8) * SPW + colg + tig + 4];
            unsigned b0 = KVs[(ks * 8 + tig)     * KVP + n0 + g];
            unsigned b1 = KVs[(ks * 8 + tig + 4) * KVP + n0 + g];
            mma_tf32(o0, o1, o2, o3, a0, a1, a2, a3, b0, b1);
        }
    }

    // ---- output: scale by 1/rowsum, write (b, n, h*32+col) ----
    {
        const int rl0 = rb2 + g, rl1 = rl0 + 8;
        const int ig0 = i0 + rl0, ig1 = i0 + rl1;
        const float s0 = rinv[rl0];
        const float s1 = rinv[rl1];
        const int cg = h * DHD + n0 + tig * 2;
        if (ig0 < NN) {
            float2 v; v.x = o0 * s0; v.y = o1 * s0;
            *(float2*)&g_o[(bz * NN + ig0) * DD + cg] = v;
        }
        if (ig1 < NN) {
            float2 v; v.x = o2 * s1; v.y = o3 * s1;
            *(float2*)&g_o[(bz * NN + ig1) * DD + cg] = v;
        }
    }
}

// ---------------- kernel 4: out projection + transpose ----------------
__global__ __launch_bounds__(256) void out_gemm(const float* __restrict__ w,
                                                float* __restrict__ out) {
    __shared__ float As[16][132];
    __shared__ float Bs[16][64];
    __shared__ float Cs[128][65];
    const int m0 = blockIdx.x * 128;
    const int c0 = blockIdx.y * 64;
    const int tid = threadIdx.x;
    const int tx = tid & 15;
    const int ty = tid >> 4;
    const int b0 = m0 / NN;
    const int n0 = m0 - b0 * NN;

    float acc[8][4];
#pragma unroll
    for (int i = 0; i < 8; i++)
#pragma unroll
        for (int j = 0; j < 4; j++) acc[i][j] = 0.f;

    for (int k0 = 0; k0 < 256; k0 += 16) {
#pragma unroll
        for (int half = 0; half < 2; half++) {
            int ml = (tid >> 2) + half * 64;
            int kq = tid & 3;
            int m = m0 + ml;
            float4 av = make_float4(0.f, 0.f, 0.f, 0.f);
            if (m < M_TOT) av = *(const float4*)&g_o[m * DD + k0 + kq * 4];
            As[kq * 4 + 0][ml] = av.x;
            As[kq * 4 + 1][ml] = av.y;
            As[kq * 4 + 2][ml] = av.z;
            As[kq * 4 + 3][ml] = av.w;
        }
#pragma unroll
        for (int i = 0; i < 4; i++) {
            int e  = tid + i * 256;
            int kk = e >> 6;
            int c  = e & 63;
            Bs[kk][c] = w[(k0 + kk) * DD + c0 + c];
        }
        __syncthreads();
#pragma unroll 8
        for (int kk = 0; kk < 16; kk++) {
            float a[8], bv[4];
            *(float4*)&a[0] = *(const float4*)&As[kk][ty * 8];
            *(float4*)&a[4] = *(const float4*)&As[kk][ty * 8 + 4];
            *(float4*)&bv[0] = *(const float4*)&Bs[kk][tx * 4];
#pragma unroll
            for (int i = 0; i < 8; i++)
#pragma unroll
                for (int j = 0; j < 4; j++) acc[i][j] = fmaf(a[i], bv[j], acc[i][j]);
        }
        __syncthreads();
    }

#pragma unroll
    for (int i = 0; i < 8; i++)
#pragma unroll
        for (int j = 0; j < 4; j++)
            Cs[ty * 8 + i][tx * 4 + j] = acc[i][j];
    __syncthreads();

#pragma unroll
    for (int r = 0; r < 32; r++) {
        int idx = tid + r * 256;
        int cl = idx >> 7;
        int ml = idx & 127;
        int n = n0 + ml;
        int bb = b0;
        if (n >= NN) { n -= NN; bb++; }
        if (bb < BB)
            out[(bb * DD + c0 + cl) * NN + n] = Cs[ml][cl];
    }
}

// ---------------- launch ----------------
extern "C" void kernel_launch(void* const* d_in, const int* in_sizes, int n_in,
                              void* d_out, int out_size) {
    const float* x      = (const float*)d_in[0];
    const float* w_qkv  = (const float*)d_in[1];
    const float* w_out  = (const float*)d_in[2];
    const float* btable = (const float*)d_in[3];
    const int*   rel    = (const int*)d_in[4];
    float* out = (float*)d_out;

    size_t attn_smem = (size_t)(IT * SPW + IT * KVP + 128 * KVP) * 4 + (IT * 4 + IT) * 4;
    cudaFuncSetAttribute(attn_kernel, cudaFuncAttributeMaxDynamicSharedMemorySize,
                         (int)attn_smem);

    qkv_gemm<<<dim3((M_TOT + 127) / 128, 768 / 128), 256>>>(x, w_qkv);
    bias_fill<<<dim3((NN + 255) / 256, NN), 256>>>(btable, rel);
    attn_kernel<<<dim3((NN + IT - 1) / IT, NH, BB), 256, attn_smem>>>();
    out_gemm<<<dim3((M_TOT + 127) / 128, DD / 64), 256>>>(w_out, out);
}